// round 1
// baseline (speedup 1.0000x reference)
#include <cuda_runtime.h>

// NerfRender integrate: per-ray sort(t) -> dt -> sigma*dt -> transmittance -> wi, rgb.
// One warp per ray. R = 65536 rays, N = 192 samples (t has N+1 = 193).
// Outputs concatenated in d_out: rgb [R,3] floats, then wi [R,192] floats.

#define NP1 193
#define NS  192
#define SORT_N 256
#define VREGS 8           // 256 / 32 lanes
#define WARPS_PER_BLOCK 8
#define ELEMS_PER_LANE 6  // 192 / 32

__device__ __forceinline__ float pos_inf() { return __int_as_float(0x7f800000); }

// ---- register-resident 256-element bitonic sort, one warp, 8 regs/lane ----
// element index i = r*32 + lane  (lane = low bits -> j<32 stages are shfl_xor,
// j>=32 stages are in-register exchanges with compile-time indices)

template <int K, int J>
__device__ __forceinline__ void bitonic_stage(float (&v)[VREGS], int lane) {
    if constexpr (J >= 32) {
        constexpr int JR = J >> 5;
#pragma unroll
        for (int r = 0; r < VREGS; r++) {
            if ((r & JR) == 0) {
                const int r2 = r | JR;
                const bool up = (((r * 32) & K) == 0);
                float a = v[r], b = v[r2];
                float mn = fminf(a, b), mx = fmaxf(a, b);
                v[r]  = up ? mn : mx;
                v[r2] = up ? mx : mn;
            }
        }
    } else {
#pragma unroll
        for (int r = 0; r < VREGS; r++) {
            float o = __shfl_xor_sync(0xffffffffu, v[r], J);
            int i = r * 32 + lane;
            bool keepMin = (((i & J) == 0) == ((i & K) == 0));
            float mn = fminf(v[r], o), mx = fmaxf(v[r], o);
            v[r] = keepMin ? mn : mx;
        }
    }
}

template <int K, int J>
__device__ __forceinline__ void bitonic_j(float (&v)[VREGS], int lane) {
    bitonic_stage<K, J>(v, lane);
    if constexpr (J > 1) bitonic_j<K, (J >> 1)>(v, lane);
}

template <int K>
__device__ __forceinline__ void bitonic_k(float (&v)[VREGS], int lane) {
    bitonic_j<K, (K >> 1)>(v, lane);
    if constexpr (K < SORT_N) bitonic_k<(K << 1)>(v, lane);
}

__global__ __launch_bounds__(WARPS_PER_BLOCK * 32)
void nerf_integrate_kernel(const float* __restrict__ t,
                           const float* __restrict__ sigma,
                           const float* __restrict__ c,
                           float* __restrict__ out_rgb,   // [R,3]
                           float* __restrict__ out_wi,    // [R,192]
                           int R) {
    const int warp = threadIdx.x >> 5;
    const int lane = threadIdx.x & 31;
    const int ray  = blockIdx.x * WARPS_PER_BLOCK + warp;
    if (ray >= R) return;

    __shared__ float sh[WARPS_PER_BLOCK][SORT_N];

    // ---- load t (coalesced, strided layout i = r*32 + lane), pad with +inf
    const float* trow = t + (size_t)ray * NP1;
    float v[VREGS];
#pragma unroll
    for (int r = 0; r < VREGS; r++) {
        int i = r * 32 + lane;
        v[r] = (i < NP1) ? __ldg(trow + i) : pos_inf();
    }

    // ---- sort 256 (193 real + 63 pads at the top)
    bitonic_k<2>(v, lane);

    // ---- stage sorted t to shared, switch to blocked layout
#pragma unroll
    for (int r = 0; r < VREGS; r++)
        sh[warp][r * 32 + lane] = v[r];
    __syncwarp();

    // ---- per-lane block of 6 samples: dt, sigma*dt, local prefix
    const int i0 = lane * ELEMS_PER_LANE;
    const float* srow = sigma + (size_t)ray * NS;

    float sdt[ELEMS_PER_LANE];
    float pfx[ELEMS_PER_LANE];
    {
        float tprev = sh[warp][i0];
        float run = 0.f;
#pragma unroll
        for (int e = 0; e < ELEMS_PER_LANE; e++) {
            float tn = sh[warp][i0 + e + 1];
            float dt = tn - tprev;
            tprev = tn;
            float s = __ldg(srow + i0 + e) * dt;
            sdt[e] = s;
            run += s;
            pfx[e] = run;
        }
    }

    // ---- warp exclusive scan of lane totals
    float tot = pfx[ELEMS_PER_LANE - 1];
    float inc = tot;
#pragma unroll
    for (int d = 1; d < 32; d <<= 1) {
        float y = __shfl_up_sync(0xffffffffu, inc, d);
        if (lane >= d) inc += y;
    }
    const float excl = inc - tot;

    // ---- weights + rgb accumulation
    const float* crow = c + (size_t)ray * NS * 3;
    float* wrow = out_wi + (size_t)ray * NS;

    float r0 = 0.f, r1 = 0.f, r2 = 0.f;
    float prevE = __expf(-excl);   // exp(-S_{i-1}) entering this lane's block
#pragma unroll
    for (int e = 0; e < ELEMS_PER_LANE; e++) {
        float E = __expf(-(excl + pfx[e]));
        float w = prevE - E;       // Ti * alpha
        prevE = E;
        wrow[i0 + e] = w;
        int ci = (i0 + e) * 3;
        r0 += w * __ldg(crow + ci + 0);
        r1 += w * __ldg(crow + ci + 1);
        r2 += w * __ldg(crow + ci + 2);
    }

    // ---- warp reduce rgb
#pragma unroll
    for (int d = 16; d > 0; d >>= 1) {
        r0 += __shfl_xor_sync(0xffffffffu, r0, d);
        r1 += __shfl_xor_sync(0xffffffffu, r1, d);
        r2 += __shfl_xor_sync(0xffffffffu, r2, d);
    }
    if (lane == 0) {
        out_rgb[(size_t)ray * 3 + 0] = r0;
        out_rgb[(size_t)ray * 3 + 1] = r1;
        out_rgb[(size_t)ray * 3 + 2] = r2;
    }
}

extern "C" void kernel_launch(void* const* d_in, const int* in_sizes, int n_in,
                              void* d_out, int out_size) {
    const float* t     = (const float*)d_in[0];
    const float* sigma = (const float*)d_in[1];
    const float* c     = (const float*)d_in[2];

    const int R = in_sizes[0] / NP1;   // 65536

    float* out_rgb = (float*)d_out;          // [R,3]
    float* out_wi  = out_rgb + (size_t)R * 3; // [R,192]

    const int blocks = (R + WARPS_PER_BLOCK - 1) / WARPS_PER_BLOCK;
    nerf_integrate_kernel<<<blocks, WARPS_PER_BLOCK * 32>>>(
        t, sigma, c, out_rgb, out_wi, R);
}

// round 2
// speedup vs baseline: 1.0181x; 1.0181x over previous
#include <cuda_runtime.h>

// NerfRender integrate, v2: blocked-layout bitonic sort (half the shuffles),
// coalesced c / wi / sigma streams. One warp per ray.
// R = 65536 rays, N = 192 samples (t has 193). Output: rgb [R,3] then wi [R,192].

#define NP1 193
#define NS  192
#define SORT_N 256
#define VR 8               // regs per lane (256 / 32)
#define WPB 8              // warps per block

__device__ __forceinline__ float pos_inf() { return __int_as_float(0x7f800000); }

// ---- blocked-layout bitonic sort: element i = (lane<<3) | r ----
// bits 0..2 = register index r, bits 3..7 = lane.
// J >= 8  -> cross-lane (shfl_xor by J>>3), direction uniform over r.
// J <  8  -> in-register exchange, no shuffle.

template <int K, int J>
__device__ __forceinline__ void bstage(float (&v)[VR], int lane) {
    if constexpr (J >= 8) {
        // cross-lane: only occurs for K >= 16
        const int lj = J >> 3;
        const bool up    = ((lane & (K >> 3)) == 0);
        const bool lower = ((lane & lj) == 0);
        const bool keepMin = (lower == up);
#pragma unroll
        for (int r = 0; r < VR; r++) {
            float o = __shfl_xor_sync(0xffffffffu, v[r], lj);
            float mn = fminf(v[r], o), mx = fmaxf(v[r], o);
            v[r] = keepMin ? mn : mx;
        }
    } else {
        bool up_lane = true;
        if constexpr (K >= 16)     up_lane = ((lane & (K >> 3)) == 0);
        else if constexpr (K == 8) up_lane = ((lane & 1) == 0);
#pragma unroll
        for (int r = 0; r < VR; r++) {
            if ((r & J) == 0) {
                const int r2 = r | J;
                bool up;
                if constexpr (K <= 4) up = ((r & K) == 0);
                else                  up = up_lane;
                float a = v[r], b = v[r2];
                float mn = fminf(a, b), mx = fmaxf(a, b);
                v[r]  = up ? mn : mx;
                v[r2] = up ? mx : mn;
            }
        }
    }
}

template <int K, int J>
__device__ __forceinline__ void bj(float (&v)[VR], int lane) {
    bstage<K, J>(v, lane);
    if constexpr (J > 1) bj<K, (J >> 1)>(v, lane);
}

template <int K>
__device__ __forceinline__ void bk(float (&v)[VR], int lane) {
    bj<K, (K >> 1)>(v, lane);
    if constexpr (K < SORT_N) bk<(K << 1)>(v, lane);
}

__global__ __launch_bounds__(WPB * 32)
void nerf_integrate_kernel(const float* __restrict__ t,
                           const float* __restrict__ sigma,
                           const float* __restrict__ c,
                           float* __restrict__ out_rgb,
                           float* __restrict__ out_wi,
                           int R) {
    const int warp = threadIdx.x >> 5;
    const int lane = threadIdx.x & 31;
    const int ray  = blockIdx.x * WPB + warp;
    if (ray >= R) return;

    __shared__ float sh[WPB][SORT_N];   // t transpose, then reused for w

    // ---- 1. load t coalesced (strided), stage to shared
    const float* trow = t + (size_t)ray * NP1;
#pragma unroll
    for (int r = 0; r < VR; r++) {
        int i = r * 32 + lane;
        sh[warp][i] = (i < NP1) ? __ldg(trow + i) : pos_inf();
    }
    __syncwarp();

    // ---- 2. read blocked: lane holds t[8*lane .. 8*lane+7]
    float v[VR];
    {
        const float4* p = reinterpret_cast<const float4*>(&sh[warp][lane * VR]);
        float4 a = p[0], b = p[1];
        v[0]=a.x; v[1]=a.y; v[2]=a.z; v[3]=a.w;
        v[4]=b.x; v[5]=b.y; v[6]=b.z; v[7]=b.w;
    }

    // ---- 3. sort 256 blocked (120 shuffles total)
    bk<2>(v, lane);
    // sorted: lane l owns t[8l+r]; real data in lanes 0..24 (t[192] at lane24,r0)

    // ---- 4. boundary value t[8l+8] from next lane
    const float tnext = __shfl_down_sync(0xffffffffu, v[0], 1);

    // ---- 5. sigma (vectorized), sdt, local prefix  (lanes 0..23 own 8 samples)
    const bool active = (lane < 24);
    float sdt[VR];
    float pfx[VR];
    {
        float4 s0 = make_float4(0.f,0.f,0.f,0.f), s1 = s0;
        if (active) {
            const float4* sp = reinterpret_cast<const float4*>(sigma + (size_t)ray * NS + lane * VR);
            s0 = __ldg(sp); s1 = __ldg(sp + 1);
        }
        float sarr[VR] = {s0.x,s0.y,s0.z,s0.w,s1.x,s1.y,s1.z,s1.w};
        float run = 0.f;
#pragma unroll
        for (int e = 0; e < VR; e++) {
            float tn = (e < VR - 1) ? v[e + 1] : tnext;
            float s  = active ? sarr[e] * (tn - v[e]) : 0.f;
            sdt[e] = s;
            run += s;
            pfx[e] = run;
        }
    }

    // ---- 6. warp exclusive scan of lane totals
    float tot = pfx[VR - 1];
    float inc = tot;
#pragma unroll
    for (int d = 1; d < 32; d <<= 1) {
        float y = __shfl_up_sync(0xffffffffu, inc, d);
        if (lane >= d) inc += y;
    }
    const float excl = inc - tot;

    // ---- 7. weights (blocked), stage into shared (reuse sh)
    float w[VR];
    {
        float prevE = __expf(-excl);
#pragma unroll
        for (int e = 0; e < VR; e++) {
            float E = __expf(-(excl + pfx[e]));
            w[e] = prevE - E;
            prevE = E;
        }
    }
    __syncwarp();   // everyone done reading sh as t
    if (active) {
        float4* wp = reinterpret_cast<float4*>(&sh[warp][lane * VR]);
        wp[0] = make_float4(w[0], w[1], w[2], w[3]);
        wp[1] = make_float4(w[4], w[5], w[6], w[7]);
    }
    __syncwarp();

    // ---- 8. wi output: fully coalesced
    float* wrow = out_wi + (size_t)ray * NS;
#pragma unroll
    for (int e = 0; e < 6; e++) {
        int i = e * 32 + lane;
        wrow[i] = sh[warp][i];
    }

    // ---- 9. rgb: coalesced float4 stream over c (576 floats = 144 float4)
    const float* crow = c + (size_t)ray * NS * 3;
    const float4* crow4 = reinterpret_cast<const float4*>(crow);
    float a0 = 0.f, a1 = 0.f, a2 = 0.f;
#pragma unroll
    for (int q = 0; q < 4; q++) {
        float4 cv = __ldg(crow4 + q * 32 + lane);
        const int kbase = (q * 32 + lane) * 4;
        float cj[4] = {cv.x, cv.y, cv.z, cv.w};
#pragma unroll
        for (int j = 0; j < 4; j++) {
            int kk = kbase + j;
            int ks = (int)((unsigned)kk / 3u);
            int ch = kk - ks * 3;
            float p = sh[warp][ks] * cj[j];
            if (ch == 0)      a0 += p;
            else if (ch == 1) a1 += p;
            else              a2 += p;
        }
    }
    // tail: flat 512..575
#pragma unroll
    for (int e = 0; e < 2; e++) {
        int kk = 512 + e * 32 + lane;
        int ks = (int)((unsigned)kk / 3u);
        int ch = kk - ks * 3;
        float p = sh[warp][ks] * __ldg(crow + kk);
        if (ch == 0)      a0 += p;
        else if (ch == 1) a1 += p;
        else              a2 += p;
    }

    // ---- 10. reduce rgb across warp
#pragma unroll
    for (int d = 16; d > 0; d >>= 1) {
        a0 += __shfl_xor_sync(0xffffffffu, a0, d);
        a1 += __shfl_xor_sync(0xffffffffu, a1, d);
        a2 += __shfl_xor_sync(0xffffffffu, a2, d);
    }
    if (lane < 3) {
        float val = (lane == 0) ? a0 : ((lane == 1) ? a1 : a2);
        out_rgb[(size_t)ray * 3 + lane] = val;
    }
}

extern "C" void kernel_launch(void* const* d_in, const int* in_sizes, int n_in,
                              void* d_out, int out_size) {
    const float* t     = (const float*)d_in[0];
    const float* sigma = (const float*)d_in[1];
    const float* c     = (const float*)d_in[2];

    const int R = in_sizes[0] / NP1;

    float* out_rgb = (float*)d_out;
    float* out_wi  = out_rgb + (size_t)R * 3;

    const int blocks = (R + WPB - 1) / WPB;
    nerf_integrate_kernel<<<blocks, WPB * 32>>>(t, sigma, c, out_rgb, out_wi, R);
}

// round 3
// speedup vs baseline: 1.1997x; 1.1783x over previous
#include <cuda_runtime.h>
#include <cstdint>

// NerfRender integrate v3: predicated-FMNMX blocked bitonic sort, cp.async
// prefetch of c/sigma, compile-time-channel rgb. One warp per ray.
// R = 65536, N = 192 (t has 193). Output: rgb [R,3] then wi [R,192].

#define NP1 193
#define NS  192
#define VR  8
#define WPB 8

__device__ __forceinline__ float pos_inf() { return __int_as_float(0x7f800000); }

__device__ __forceinline__ void cp_async16(uint32_t saddr, const void* gptr) {
    asm volatile("cp.async.cg.shared.global [%0], [%1], 16;\n" :: "r"(saddr), "l"(gptr));
}
__device__ __forceinline__ void cp_async_commit() {
    asm volatile("cp.async.commit_group;\n" ::: "memory");
}
__device__ __forceinline__ void cp_async_wait_all() {
    asm volatile("cp.async.wait_group 0;\n" ::: "memory");
}

// ---- blocked bitonic, element i = (lane<<3)|r, predicated FMNMX form ----
template <int K, int J>
__device__ __forceinline__ void bstage(float (&v)[VR], int lane) {
    if constexpr (J >= 8) {                       // cross-lane (K >= 16 here)
        const int lj = J >> 3;
        const bool up = ((lane & (K >> 3)) == 0);
        const bool keepMin = (((lane & lj) == 0) == up);
#pragma unroll
        for (int r = 0; r < VR; r++) {
            float o = __shfl_xor_sync(0xffffffffu, v[r], lj);
            v[r] = keepMin ? fminf(v[r], o) : fmaxf(v[r], o);   // 1 FMNMX(P)
        }
    } else if constexpr (K <= 4) {                // direction compile-time
#pragma unroll
        for (int r = 0; r < VR; r++) {
            if ((r & J) == 0) {
                const int r2 = r | J;
                float a = v[r], b = v[r2];
                if ((r & K) == 0) { v[r] = fminf(a, b); v[r2] = fmaxf(a, b); }
                else              { v[r] = fmaxf(a, b); v[r2] = fminf(a, b); }
            }
        }
    } else {                                      // in-register, runtime dir
        const bool up = (K == 8) ? ((lane & 1) == 0) : ((lane & (K >> 3)) == 0);
#pragma unroll
        for (int r = 0; r < VR; r++) {
            if ((r & J) == 0) {
                const int r2 = r | J;
                float a = v[r], b = v[r2];
                v[r]  = up ? fminf(a, b) : fmaxf(a, b);   // FMNMX(P)
                v[r2] = up ? fmaxf(a, b) : fminf(a, b);   // FMNMX(!P)
            }
        }
    }
}

template <int K, int J>
__device__ __forceinline__ void bj(float (&v)[VR], int lane) {
    bstage<K, J>(v, lane);
    if constexpr (J > 1) bj<K, (J >> 1)>(v, lane);
}
template <int K>
__device__ __forceinline__ void bk(float (&v)[VR], int lane) {
    bj<K, (K >> 1)>(v, lane);
    if constexpr (K < 256) bk<(K << 1)>(v, lane);
}

// shared per warp: [0..256) t/w workspace, [256..832) c, [832..1024) sigma
#define SH_C 256
#define SH_S 832

__global__ __launch_bounds__(WPB * 32)
void nerf_integrate_kernel(const float* __restrict__ t,
                           const float* __restrict__ sigma,
                           const float* __restrict__ c,
                           float* __restrict__ out_rgb,
                           float* __restrict__ out_wi,
                           int R) {
    const int warp = threadIdx.x >> 5;
    const int lane = threadIdx.x & 31;
    const int ray  = blockIdx.x * WPB + warp;
    if (ray >= R) return;

    __shared__ float sh[WPB][1024];
    float* shw = sh[warp];

    const float* trow  = t + (size_t)ray * NP1;
    const float* srow  = sigma + (size_t)ray * NS;
    const float* crow  = c + (size_t)ray * NS * 3;

    // ---- 1. t loads (critical path) -----------------------------------
    float tv[6];
#pragma unroll
    for (int r = 0; r < 6; r++) tv[r] = __ldg(trow + r * 32 + lane);
    float t192 = (lane == 0) ? __ldg(trow + 192) : pos_inf();

    // ---- 2. prefetch c (144 float4) and sigma (48 float4) via cp.async -
    {
        const uint32_t shc_a = (uint32_t)__cvta_generic_to_shared(shw + SH_C);
        const uint32_t shs_a = (uint32_t)__cvta_generic_to_shared(shw + SH_S);
        const float4* c4 = reinterpret_cast<const float4*>(crow);
        const float4* s4 = reinterpret_cast<const float4*>(srow);
#pragma unroll
        for (int e = 0; e < 4; e++)
            cp_async16(shc_a + (e * 32 + lane) * 16, c4 + e * 32 + lane);
        if (lane < 16)
            cp_async16(shc_a + (128 + lane) * 16, c4 + 128 + lane);
        cp_async16(shs_a + lane * 16, s4 + lane);
        if (lane < 16)
            cp_async16(shs_a + (32 + lane) * 16, s4 + 32 + lane);
        cp_async_commit();
    }

    // ---- 3. stage t to shared, reload blocked -------------------------
#pragma unroll
    for (int r = 0; r < 6; r++) shw[r * 32 + lane] = tv[r];
    shw[192 + lane] = t192;          // lane0 -> t[192], rest +inf
    shw[224 + lane] = pos_inf();
    __syncwarp();

    float v[VR];
    {
        const float4* p = reinterpret_cast<const float4*>(shw + lane * VR);
        float4 a = p[0], b = p[1];
        v[0]=a.x; v[1]=a.y; v[2]=a.z; v[3]=a.w;
        v[4]=b.x; v[5]=b.y; v[6]=b.z; v[7]=b.w;
    }

    // ---- 4. sort 256 ---------------------------------------------------
    bk<2>(v, lane);
    const float tnext = __shfl_down_sync(0xffffffffu, v[0], 1);

    // ---- 5. sigma (from shared), sdt prefix ----------------------------
    cp_async_wait_all();
    __syncwarp();

    const bool active = (lane < 24);
    float pfx[VR];
    {
        float sarr[VR];
        if (active) {
            const float4* sp = reinterpret_cast<const float4*>(shw + SH_S + lane * VR);
            float4 s0 = sp[0], s1 = sp[1];
            sarr[0]=s0.x; sarr[1]=s0.y; sarr[2]=s0.z; sarr[3]=s0.w;
            sarr[4]=s1.x; sarr[5]=s1.y; sarr[6]=s1.z; sarr[7]=s1.w;
        } else {
#pragma unroll
            for (int e = 0; e < VR; e++) sarr[e] = 0.f;
        }
        float run = 0.f;
#pragma unroll
        for (int e = 0; e < VR; e++) {
            float tn = (e < VR - 1) ? v[e + 1] : tnext;
            float s  = active ? sarr[e] * (tn - v[e]) : 0.f;
            run += s;
            pfx[e] = run;
        }
    }

    // ---- 6. warp exclusive scan ----------------------------------------
    float tot = pfx[VR - 1];
    float inc = tot;
#pragma unroll
    for (int d = 1; d < 32; d <<= 1) {
        float y = __shfl_up_sync(0xffffffffu, inc, d);
        if (lane >= d) inc += y;
    }
    const float excl = inc - tot;

    // ---- 7. weights ------------------------------------------------------
    float w[VR];
    {
        float prevE = __expf(-excl);
#pragma unroll
        for (int e = 0; e < VR; e++) {
            float E = __expf(-(excl + pfx[e]));
            w[e] = prevE - E;
            prevE = E;
        }
    }

    // ---- 8. rgb: per-lane own samples, compile-time channels ------------
    float a0 = 0.f, a1 = 0.f, a2 = 0.f;
    if (active) {
        const float4* cp = reinterpret_cast<const float4*>(shw + SH_C + lane * 24);
        float cf[24];
#pragma unroll
        for (int q = 0; q < 6; q++) {
            float4 cv = cp[q];
            cf[q*4+0]=cv.x; cf[q*4+1]=cv.y; cf[q*4+2]=cv.z; cf[q*4+3]=cv.w;
        }
#pragma unroll
        for (int e = 0; e < VR; e++) {
            a0 += w[e] * cf[3*e+0];
            a1 += w[e] * cf[3*e+1];
            a2 += w[e] * cf[3*e+2];
        }
    }

    // ---- 9. stage w, coalesced wi out -----------------------------------
    __syncwarp();
    if (active) {
        float4* wp = reinterpret_cast<float4*>(shw + lane * VR);
        wp[0] = make_float4(w[0], w[1], w[2], w[3]);
        wp[1] = make_float4(w[4], w[5], w[6], w[7]);
    }
    __syncwarp();
    float* wrow = out_wi + (size_t)ray * NS;
#pragma unroll
    for (int e = 0; e < 6; e++) {
        int i = e * 32 + lane;
        wrow[i] = shw[i];
    }

    // ---- 10. reduce rgb ---------------------------------------------------
#pragma unroll
    for (int d = 16; d > 0; d >>= 1) {
        a0 += __shfl_xor_sync(0xffffffffu, a0, d);
        a1 += __shfl_xor_sync(0xffffffffu, a1, d);
        a2 += __shfl_xor_sync(0xffffffffu, a2, d);
    }
    if (lane < 3) {
        float val = (lane == 0) ? a0 : ((lane == 1) ? a1 : a2);
        out_rgb[(size_t)ray * 3 + lane] = val;
    }
}

extern "C" void kernel_launch(void* const* d_in, const int* in_sizes, int n_in,
                              void* d_out, int out_size) {
    const float* t     = (const float*)d_in[0];
    const float* sigma = (const float*)d_in[1];
    const float* c     = (const float*)d_in[2];

    const int R = in_sizes[0] / NP1;

    float* out_rgb = (float*)d_out;
    float* out_wi  = out_rgb + (size_t)R * 3;

    const int blocks = (R + WPB - 1) / WPB;
    nerf_integrate_kernel<<<blocks, WPB * 32>>>(t, sigma, c, out_rgb, out_wi, R);
}